// round 1
// baseline (speedup 1.0000x reference)
#include <cuda_runtime.h>
#include <math.h>

// Problem constants
constexpr int B_  = 2;
constexpr int S_  = 4096;
constexpr int D_  = 1024;
constexpr int H_  = 16;
constexpr int HD_ = 64;
constexpr int MTOT = B_ * S_;   // 8192

// Scratch (alloc-free rule: __device__ globals)
__device__ float g_q[MTOT * D_];
__device__ float g_k[MTOT * D_];
__device__ float g_v[MTOT * D_];
__device__ float g_att[MTOT * D_];

// ---------------------------------------------------------------------------
// GEMM: Y[M,N] = X[M,K] @ W[N,K]^T + bias[N]   (M=8192, N=K=1024)
// 128x128 tile, BK=32, 256 threads, 8x8 microtile (2x2 of 4x4 split tiles)
// ---------------------------------------------------------------------------
__global__ __launch_bounds__(256) void gemm_bias_kernel(
    const float* __restrict__ X, const float* __restrict__ W,
    const float* __restrict__ bias, float* __restrict__ Y)
{
    __shared__ float Xs[128 * 33];
    __shared__ float Ws[128 * 33];

    const int m0 = blockIdx.y * 128;
    const int n0 = blockIdx.x * 128;
    const int tid = threadIdx.x;
    const int tx = tid & 15;
    const int ty = tid >> 4;

    float acc[8][8];
#pragma unroll
    for (int i = 0; i < 8; i++)
#pragma unroll
        for (int j = 0; j < 8; j++) acc[i][j] = 0.0f;

    int rofs[8], cofs[8];
#pragma unroll
    for (int i = 0; i < 4; i++) {
        rofs[i]     = (4 * ty + i) * 33;
        rofs[i + 4] = (64 + 4 * ty + i) * 33;
        cofs[i]     = (4 * tx + i) * 33;
        cofs[i + 4] = (64 + 4 * tx + i) * 33;
    }

    for (int kt = 0; kt < 1024; kt += 32) {
        __syncthreads();
        // load 128x32 of X and W (as float4, scalar STS with +1 pad)
#pragma unroll
        for (int it = 0; it < 4; it++) {
            int i = tid + it * 256;
            int row = i >> 3;
            int c4  = (i & 7) * 4;
            float4 vx = *(const float4*)(X + (size_t)(m0 + row) * 1024 + kt + c4);
            float* dx = &Xs[row * 33 + c4];
            dx[0] = vx.x; dx[1] = vx.y; dx[2] = vx.z; dx[3] = vx.w;
            float4 vw = *(const float4*)(W + (size_t)(n0 + row) * 1024 + kt + c4);
            float* dw = &Ws[row * 33 + c4];
            dw[0] = vw.x; dw[1] = vw.y; dw[2] = vw.z; dw[3] = vw.w;
        }
        __syncthreads();

#pragma unroll 8
        for (int kk = 0; kk < 32; kk++) {
            float a[8], bb[8];
#pragma unroll
            for (int i = 0; i < 8; i++) a[i]  = Xs[rofs[i] + kk];
#pragma unroll
            for (int j = 0; j < 8; j++) bb[j] = Ws[cofs[j] + kk];
#pragma unroll
            for (int i = 0; i < 8; i++)
#pragma unroll
                for (int j = 0; j < 8; j++)
                    acc[i][j] = fmaf(a[i], bb[j], acc[i][j]);
        }
    }

    // epilogue
#pragma unroll
    for (int i = 0; i < 8; i++) {
        int row = (i < 4) ? (4 * ty + i) : (64 + 4 * ty + (i - 4));
#pragma unroll
        for (int j = 0; j < 8; j++) {
            int col = (j < 4) ? (4 * tx + j) : (64 + 4 * tx + (j - 4));
            Y[(size_t)(m0 + row) * 1024 + n0 + col] = acc[i][j] + bias[n0 + col];
        }
    }
}

// ---------------------------------------------------------------------------
// Flash-style attention (fp32). One CTA = (b, h, 128-query tile).
// K/V tiles of 64 keys, online softmax, P staged in smem.
// ---------------------------------------------------------------------------
__global__ __launch_bounds__(256) void attn_kernel(
    const float* __restrict__ q, const float* __restrict__ k,
    const float* __restrict__ v, float* __restrict__ out)
{
    extern __shared__ float sm[];
    float* Qs = sm;                   // 128 x 65
    float* Ks = Qs + 128 * 65;        // 64 x 65
    float* Vs = Ks + 64 * 65;         // 64 x 65
    float* Ps = Vs + 64 * 65;         // 128 x 65

    const int q0 = blockIdx.x * 128;
    const int h  = blockIdx.y;
    const int b  = blockIdx.z;
    const int tid = threadIdx.x;
    const int tx = tid & 15;
    const int ty = tid >> 4;
    const float scale = 0.125f;  // 1/sqrt(64)

    int rows[8], roff[8];
#pragma unroll
    for (int i = 0; i < 8; i++) {
        rows[i] = (i < 4) ? (4 * ty + i) : (64 + 4 * ty + (i - 4));
        roff[i] = rows[i] * 65;
    }

    // load Q tile: 128 rows x 64 cols
#pragma unroll
    for (int it = 0; it < 8; it++) {
        int i = tid + it * 256;
        int r = i >> 4;
        int c4 = (i & 15) * 4;
        float4 t = *(const float4*)(q + ((size_t)(b * S_ + q0 + r)) * D_ + h * 64 + c4);
        float* d = &Qs[r * 65 + c4];
        d[0] = t.x; d[1] = t.y; d[2] = t.z; d[3] = t.w;
    }

    float m_i[8], l_i[8], o[8][4];
#pragma unroll
    for (int i = 0; i < 8; i++) {
        m_i[i] = -INFINITY;
        l_i[i] = 0.0f;
#pragma unroll
        for (int j = 0; j < 4; j++) o[i][j] = 0.0f;
    }

    for (int kt = 0; kt < S_; kt += 64) {
        __syncthreads();
        // load K & V tiles: 64 rows x 64 cols each
#pragma unroll
        for (int it = 0; it < 4; it++) {
            int i = tid + it * 256;
            int r = i >> 4;
            int c4 = (i & 15) * 4;
            size_t gi = ((size_t)(b * S_ + kt + r)) * D_ + h * 64 + c4;
            float4 tk = *(const float4*)(k + gi);
            float* dk = &Ks[r * 65 + c4];
            dk[0] = tk.x; dk[1] = tk.y; dk[2] = tk.z; dk[3] = tk.w;
            float4 tv = *(const float4*)(v + gi);
            float* dv = &Vs[r * 65 + c4];
            dv[0] = tv.x; dv[1] = tv.y; dv[2] = tv.z; dv[3] = tv.w;
        }
        __syncthreads();

        // scores tile: s[8][4] = Q(rows) . K(cols)
        float s[8][4];
#pragma unroll
        for (int i = 0; i < 8; i++)
#pragma unroll
            for (int j = 0; j < 4; j++) s[i][j] = 0.0f;

#pragma unroll 4
        for (int kk = 0; kk < 64; kk++) {
            float a[8], bb[4];
#pragma unroll
            for (int i = 0; i < 8; i++) a[i] = Qs[roff[i] + kk];
#pragma unroll
            for (int j = 0; j < 4; j++) bb[j] = Ks[(4 * tx + j) * 65 + kk];
#pragma unroll
            for (int i = 0; i < 8; i++)
#pragma unroll
                for (int j = 0; j < 4; j++)
                    s[i][j] = fmaf(a[i], bb[j], s[i][j]);
        }

        // online softmax per row (16-lane row groups)
#pragma unroll
        for (int i = 0; i < 8; i++) {
            float mx = -INFINITY;
#pragma unroll
            for (int j = 0; j < 4; j++) {
                s[i][j] *= scale;
                mx = fmaxf(mx, s[i][j]);
            }
#pragma unroll
            for (int off = 8; off > 0; off >>= 1)
                mx = fmaxf(mx, __shfl_xor_sync(0xffffffffu, mx, off));
            float mnew = fmaxf(m_i[i], mx);
            float corr = __expf(m_i[i] - mnew);
            m_i[i] = mnew;
            float ps = 0.0f;
#pragma unroll
            for (int j = 0; j < 4; j++) {
                float p = __expf(s[i][j] - mnew);
                Ps[roff[i] + 4 * tx + j] = p;
                ps += p;
            }
#pragma unroll
            for (int off = 8; off > 0; off >>= 1)
                ps += __shfl_xor_sync(0xffffffffu, ps, off);
            l_i[i] = l_i[i] * corr + ps;
#pragma unroll
            for (int j = 0; j < 4; j++) o[i][j] *= corr;
        }
        __syncthreads();

        // O += P @ V
#pragma unroll 4
        for (int kk = 0; kk < 64; kk++) {
            float bb[4];
#pragma unroll
            for (int j = 0; j < 4; j++) bb[j] = Vs[kk * 65 + 4 * tx + j];
#pragma unroll
            for (int i = 0; i < 8; i++) {
                float a = Ps[roff[i] + kk];
#pragma unroll
                for (int j = 0; j < 4; j++)
                    o[i][j] = fmaf(a, bb[j], o[i][j]);
            }
        }
    }

    // final normalize + store
#pragma unroll
    for (int i = 0; i < 8; i++) {
        float inv = 1.0f / l_i[i];
        size_t base = ((size_t)(b * S_ + q0 + rows[i])) * D_ + h * 64 + 4 * tx;
#pragma unroll
        for (int j = 0; j < 4; j++)
            out[base + j] = o[i][j] * inv;
    }
}

// ---------------------------------------------------------------------------
// Launch
// ---------------------------------------------------------------------------
extern "C" void kernel_launch(void* const* d_in, const int* in_sizes, int n_in,
                              void* d_out, int out_size)
{
    const float* x  = (const float*)d_in[0];
    const float* Wq = (const float*)d_in[1];
    const float* bq = (const float*)d_in[2];
    const float* Wk = (const float*)d_in[3];
    const float* bk = (const float*)d_in[4];
    const float* Wv = (const float*)d_in[5];
    const float* bv = (const float*)d_in[6];
    const float* Wo = (const float*)d_in[7];
    const float* bo = (const float*)d_in[8];

    float *qp, *kp, *vp, *ap;
    cudaGetSymbolAddress((void**)&qp, g_q);
    cudaGetSymbolAddress((void**)&kp, g_k);
    cudaGetSymbolAddress((void**)&vp, g_v);
    cudaGetSymbolAddress((void**)&ap, g_att);

    const int smem_attn = (128 * 65 + 64 * 65 + 64 * 65 + 128 * 65) * (int)sizeof(float);
    cudaFuncSetAttribute(attn_kernel, cudaFuncAttributeMaxDynamicSharedMemorySize, smem_attn);

    dim3 gg(1024 / 128, MTOT / 128);  // (8, 64)
    gemm_bias_kernel<<<gg, 256>>>(x, Wq, bq, qp);
    gemm_bias_kernel<<<gg, 256>>>(x, Wk, bk, kp);
    gemm_bias_kernel<<<gg, 256>>>(x, Wv, bv, vp);

    dim3 ga(S_ / 128, H_, B_);        // (32, 16, 2)
    attn_kernel<<<ga, 256, smem_attn>>>(qp, kp, vp, ap);

    gemm_bias_kernel<<<gg, 256>>>(ap, Wo, bo, (float*)d_out);
}

// round 4
// speedup vs baseline: 3.0933x; 3.0933x over previous
#include <cuda_runtime.h>
#include <math.h>
#include <stdint.h>

// Problem constants
constexpr int B_  = 2;
constexpr int S_  = 4096;
constexpr int D_  = 1024;
constexpr int H_  = 16;
constexpr int MTOT = B_ * S_;   // 8192

// Scratch (alloc-free rule: __device__ globals)
__device__ float g_q[MTOT * D_];
__device__ float g_k[MTOT * D_];
__device__ float g_v[MTOT * D_];
__device__ float g_att[MTOT * D_];

// ---------------------------------------------------------------------------
// Helpers (portable sm_80+ PTX only — NO tcgen05 / 103a-gated instructions;
// ptxas in this harness targets plain sm_103, which rejects the 'a' feature set)
// ---------------------------------------------------------------------------
__device__ __forceinline__ uint32_t f2tf32(float f) {
    uint32_t u;
    asm("cvt.rna.tf32.f32 %0, %1;" : "=r"(u) : "f"(f));
    return u;
}

// D += A(16x8,row) * B(8x8,col)   tf32 inputs, f32 accum
__device__ __forceinline__ void mma_tf32(float* d, const uint32_t* a,
                                         uint32_t b0, uint32_t b1) {
    asm volatile(
        "mma.sync.aligned.m16n8k8.row.col.f32.tf32.tf32.f32 "
        "{%0,%1,%2,%3}, {%4,%5,%6,%7}, {%8,%9}, {%0,%1,%2,%3};"
        : "+f"(d[0]), "+f"(d[1]), "+f"(d[2]), "+f"(d[3])
        : "r"(a[0]), "r"(a[1]), "r"(a[2]), "r"(a[3]), "r"(b0), "r"(b1));
}

// ===========================================================================
// GEMM: Y[M,N] = X[M,K] @ W[N,K]^T + bias[N]  (M=8192, N=K=1024), tf32 mma
// 128x128 tile, BK=32, 256 threads = 8 warps (2x4), warp tile 64x32.
// smem row stride 36 -> conflict-free fragment loads (bank = 4*g + t4).
// ===========================================================================
__global__ __launch_bounds__(256) void gemm_mma_kernel(
    const float* __restrict__ X, const float* __restrict__ W,
    const float* __restrict__ bias, float* __restrict__ Y)
{
    __shared__ uint32_t Xs[128][36];
    __shared__ uint32_t Ws[128][36];

    const int tid  = threadIdx.x;
    const int m0   = blockIdx.y * 128;
    const int n0   = blockIdx.x * 128;
    const int wid  = tid >> 5;
    const int lane = tid & 31;
    const int g    = lane >> 2;
    const int t4   = lane & 3;
    const int wm   = (wid >> 2) * 64;
    const int wn   = (wid & 3) * 32;

    const int lrow = tid >> 3;          // 0..31
    const int lc4  = (tid & 7) * 4;     // 0,4,..,28

    float acc[4][4][4];
#pragma unroll
    for (int mt = 0; mt < 4; mt++)
#pragma unroll
        for (int nt = 0; nt < 4; nt++)
#pragma unroll
            for (int r = 0; r < 4; r++) acc[mt][nt][r] = 0.0f;

    for (int kt = 0; kt < 1024; kt += 32) {
        __syncthreads();
#pragma unroll
        for (int r = 0; r < 4; r++) {
            int row = lrow + r * 32;
            float4 vx = *(const float4*)(X + (size_t)(m0 + row) * 1024 + kt + lc4);
            uint4 ux = { f2tf32(vx.x), f2tf32(vx.y), f2tf32(vx.z), f2tf32(vx.w) };
            *(uint4*)&Xs[row][lc4] = ux;
            float4 vw = *(const float4*)(W + (size_t)(n0 + row) * 1024 + kt + lc4);
            uint4 uw = { f2tf32(vw.x), f2tf32(vw.y), f2tf32(vw.z), f2tf32(vw.w) };
            *(uint4*)&Ws[row][lc4] = uw;
        }
        __syncthreads();

#pragma unroll
        for (int ks = 0; ks < 4; ks++) {
            const int kb = ks * 8;
            uint32_t a[4][4];
#pragma unroll
            for (int mt = 0; mt < 4; mt++) {
                int r = wm + mt * 16;
                a[mt][0] = Xs[r + g][kb + t4];
                a[mt][1] = Xs[r + g + 8][kb + t4];
                a[mt][2] = Xs[r + g][kb + t4 + 4];
                a[mt][3] = Xs[r + g + 8][kb + t4 + 4];
            }
#pragma unroll
            for (int nt = 0; nt < 4; nt++) {
                uint32_t b0 = Ws[wn + nt * 8 + g][kb + t4];
                uint32_t b1 = Ws[wn + nt * 8 + g][kb + t4 + 4];
#pragma unroll
                for (int mt = 0; mt < 4; mt++)
                    mma_tf32(acc[mt][nt], a[mt], b0, b1);
            }
        }
    }

    // epilogue: D-fragment (row g / g+8, cols 2*t4, 2*t4+1) + bias, float2 STG
#pragma unroll
    for (int mt = 0; mt < 4; mt++) {
#pragma unroll
        for (int nt = 0; nt < 4; nt++) {
            int col = n0 + wn + nt * 8 + 2 * t4;
            float bx = __ldg(bias + col);
            float by = __ldg(bias + col + 1);
            int r0 = m0 + wm + mt * 16 + g;
            float2 v0 = { acc[mt][nt][0] + bx, acc[mt][nt][1] + by };
            *(float2*)(Y + (size_t)r0 * 1024 + col) = v0;
            float2 v1 = { acc[mt][nt][2] + bx, acc[mt][nt][3] + by };
            *(float2*)(Y + (size_t)(r0 + 8) * 1024 + col) = v1;
        }
    }
}

// ===========================================================================
// Flash attention with tf32 mma.sync.
// CTA = (b, h, 256-query tile), 256 threads = 8 warps, warp owns 32 q rows.
// K-tile = 64 keys. Scores/O in mma fragments; P via smem (tf32).
// smem strides 68 -> conflict-free A/B fragment loads.
// ===========================================================================
constexpr int QS_OFF = 0;              // 256 x 68
constexpr int KS_OFF = QS_OFF + 256 * 68;   // 64 x 68
constexpr int VS_OFF = KS_OFF + 64 * 68;    // 64 x 68
constexpr int PS_OFF = VS_OFF + 64 * 68;    // 256 x 68
constexpr int ATTN_SMEM_U32 = PS_OFF + 256 * 68;
constexpr int ATTN_SMEM = ATTN_SMEM_U32 * 4;   // 174080 B

__global__ __launch_bounds__(256) void attn_mma_kernel(
    const float* __restrict__ q, const float* __restrict__ k,
    const float* __restrict__ v, float* __restrict__ out)
{
    extern __shared__ uint32_t sm[];
    uint32_t* Qs = sm + QS_OFF;
    uint32_t* Ks = sm + KS_OFF;
    uint32_t* Vs = sm + VS_OFF;
    uint32_t* Ps = sm + PS_OFF;

    const int q0   = blockIdx.x * 256;
    const int h    = blockIdx.y;
    const int b    = blockIdx.z;
    const int tid  = threadIdx.x;
    const int wid  = tid >> 5;
    const int lane = tid & 31;
    const int g    = lane >> 2;
    const int t4   = lane & 3;
    const int wr   = wid * 32;          // warp's q-row base (2 m-tiles of 16)

    // ---- load Q tile (256 x 64), scaled by 1/8 (exact), tf32-rounded ----
#pragma unroll
    for (int it = 0; it < 16; it++) {
        int flat = tid + it * 256;
        int row = flat >> 4;
        int c4  = (flat & 15) * 4;
        float4 t = *(const float4*)(q + ((size_t)(b * S_ + q0 + row)) * D_ + h * 64 + c4);
        uint4 u = { f2tf32(t.x * 0.125f), f2tf32(t.y * 0.125f),
                    f2tf32(t.z * 0.125f), f2tf32(t.w * 0.125f) };
        *(uint4*)&Qs[row * 68 + c4] = u;
    }

    float m_i[2][2], l_i[2][2], o[2][8][4];
#pragma unroll
    for (int mt = 0; mt < 2; mt++)
#pragma unroll
        for (int hf = 0; hf < 2; hf++) { m_i[mt][hf] = -INFINITY; l_i[mt][hf] = 0.0f; }
#pragma unroll
    for (int mt = 0; mt < 2; mt++)
#pragma unroll
        for (int nt = 0; nt < 8; nt++)
#pragma unroll
            for (int r = 0; r < 4; r++) o[mt][nt][r] = 0.0f;

    for (int kt0 = 0; kt0 < S_; kt0 += 64) {
        __syncthreads();
        // ---- load K,V tiles (64 x 64 each), tf32-rounded ----
#pragma unroll
        for (int it = 0; it < 4; it++) {
            int flat = tid + it * 256;
            int row = flat >> 4;
            int c4  = (flat & 15) * 4;
            size_t gi = ((size_t)(b * S_ + kt0 + row)) * D_ + h * 64 + c4;
            float4 tk = *(const float4*)(k + gi);
            uint4 uk = { f2tf32(tk.x), f2tf32(tk.y), f2tf32(tk.z), f2tf32(tk.w) };
            *(uint4*)&Ks[row * 68 + c4] = uk;
            float4 tv = *(const float4*)(v + gi);
            uint4 uv = { f2tf32(tv.x), f2tf32(tv.y), f2tf32(tv.z), f2tf32(tv.w) };
            *(uint4*)&Vs[row * 68 + c4] = uv;
        }
        __syncthreads();

        // ---- S = Q . K^T  (per warp: 32 q x 64 keys) ----
        float s[2][8][4];
#pragma unroll
        for (int mt = 0; mt < 2; mt++)
#pragma unroll
            for (int nt = 0; nt < 8; nt++)
#pragma unroll
                for (int r = 0; r < 4; r++) s[mt][nt][r] = 0.0f;

#pragma unroll
        for (int ks = 0; ks < 8; ks++) {
            const int kb = ks * 8;
            uint32_t a[2][4];
#pragma unroll
            for (int mt = 0; mt < 2; mt++) {
                int r = wr + mt * 16;
                a[mt][0] = Qs[(r + g) * 68 + kb + t4];
                a[mt][1] = Qs[(r + g + 8) * 68 + kb + t4];
                a[mt][2] = Qs[(r + g) * 68 + kb + t4 + 4];
                a[mt][3] = Qs[(r + g + 8) * 68 + kb + t4 + 4];
            }
#pragma unroll
            for (int nt = 0; nt < 8; nt++) {
                uint32_t b0 = Ks[(nt * 8 + g) * 68 + kb + t4];
                uint32_t b1 = Ks[(nt * 8 + g) * 68 + kb + t4 + 4];
#pragma unroll
                for (int mt = 0; mt < 2; mt++)
                    mma_tf32(s[mt][nt], a[mt], b0, b1);
            }
        }

        // ---- online softmax (rows: g [regs 0,1], g+8 [regs 2,3]) ----
#pragma unroll
        for (int mt = 0; mt < 2; mt++) {
#pragma unroll
            for (int hf = 0; hf < 2; hf++) {
                const int r0 = hf * 2;
                float mx = -INFINITY;
#pragma unroll
                for (int nt = 0; nt < 8; nt++)
                    mx = fmaxf(mx, fmaxf(s[mt][nt][r0], s[mt][nt][r0 + 1]));
                mx = fmaxf(mx, __shfl_xor_sync(0xffffffffu, mx, 1));
                mx = fmaxf(mx, __shfl_xor_sync(0xffffffffu, mx, 2));
                float mnew = fmaxf(m_i[mt][hf], mx);
                float corr = __expf(m_i[mt][hf] - mnew);
                m_i[mt][hf] = mnew;
                int prow = wr + mt * 16 + g + 8 * hf;
                float ps = 0.0f;
#pragma unroll
                for (int nt = 0; nt < 8; nt++) {
                    float p0 = __expf(s[mt][nt][r0] - mnew);
                    float p1 = __expf(s[mt][nt][r0 + 1] - mnew);
                    ps += p0 + p1;
                    Ps[prow * 68 + nt * 8 + 2 * t4]     = f2tf32(p0);
                    Ps[prow * 68 + nt * 8 + 2 * t4 + 1] = f2tf32(p1);
                }
                ps += __shfl_xor_sync(0xffffffffu, ps, 1);
                ps += __shfl_xor_sync(0xffffffffu, ps, 2);
                l_i[mt][hf] = l_i[mt][hf] * corr + ps;
#pragma unroll
                for (int nt = 0; nt < 8; nt++) {
                    o[mt][nt][r0]     *= corr;
                    o[mt][nt][r0 + 1] *= corr;
                }
            }
        }
        __syncwarp();   // Ps (warp-private rows) visible to all lanes

        // ---- O += P . V ----
#pragma unroll
        for (int ks = 0; ks < 8; ks++) {
            const int kb = ks * 8;
            uint32_t a[2][4];
#pragma unroll
            for (int mt = 0; mt < 2; mt++) {
                int r = wr + mt * 16;
                a[mt][0] = Ps[(r + g) * 68 + kb + t4];
                a[mt][1] = Ps[(r + g + 8) * 68 + kb + t4];
                a[mt][2] = Ps[(r + g) * 68 + kb + t4 + 4];
                a[mt][3] = Ps[(r + g + 8) * 68 + kb + t4 + 4];
            }
#pragma unroll
            for (int nt = 0; nt < 8; nt++) {
                uint32_t b0 = Vs[(kb + t4) * 68 + nt * 8 + g];
                uint32_t b1 = Vs[(kb + t4 + 4) * 68 + nt * 8 + g];
#pragma unroll
                for (int mt = 0; mt < 2; mt++)
                    mma_tf32(o[mt][nt], a[mt], b0, b1);
            }
        }
        __syncwarp();   // PV reads done before next tile's Ps writes
    }

    // ---- epilogue: normalize, store ----
#pragma unroll
    for (int mt = 0; mt < 2; mt++) {
#pragma unroll
        for (int hf = 0; hf < 2; hf++) {
            const int r0 = hf * 2;
            float inv = 1.0f / l_i[mt][hf];
            int row = q0 + wr + mt * 16 + g + 8 * hf;
            size_t base = ((size_t)(b * S_ + row)) * D_ + h * 64;
#pragma unroll
            for (int nt = 0; nt < 8; nt++) {
                float2 vv = { o[mt][nt][r0] * inv, o[mt][nt][r0 + 1] * inv };
                *(float2*)(out + base + nt * 8 + 2 * t4) = vv;
            }
        }
    }
}

// ---------------------------------------------------------------------------
// Launch
// ---------------------------------------------------------------------------
extern "C" void kernel_launch(void* const* d_in, const int* in_sizes, int n_in,
                              void* d_out, int out_size)
{
    const float* x  = (const float*)d_in[0];
    const float* Wq = (const float*)d_in[1];
    const float* bq = (const float*)d_in[2];
    const float* Wk = (const float*)d_in[3];
    const float* bk = (const float*)d_in[4];
    const float* Wv = (const float*)d_in[5];
    const float* bv = (const float*)d_in[6];
    const float* Wo = (const float*)d_in[7];
    const float* bo = (const float*)d_in[8];

    float *qp, *kp, *vp, *ap;
    cudaGetSymbolAddress((void**)&qp, g_q);
    cudaGetSymbolAddress((void**)&kp, g_k);
    cudaGetSymbolAddress((void**)&vp, g_v);
    cudaGetSymbolAddress((void**)&ap, g_att);

    cudaFuncSetAttribute(attn_mma_kernel, cudaFuncAttributeMaxDynamicSharedMemorySize, ATTN_SMEM);

    dim3 gg(1024 / 128, MTOT / 128);  // (8, 64)
    gemm_mma_kernel<<<gg, 256>>>(x, Wq, bq, qp);
    gemm_mma_kernel<<<gg, 256>>>(x, Wk, bk, kp);
    gemm_mma_kernel<<<gg, 256>>>(x, Wv, bv, vp);

    dim3 ga(S_ / 256, H_, B_);        // (16, 16, 2)
    attn_mma_kernel<<<ga, 256, ATTN_SMEM>>>(qp, kp, vp, ap);

    gemm_mma_kernel<<<gg, 256>>>(ap, Wo, bo, (float*)d_out);
}